// round 2
// baseline (speedup 1.0000x reference)
#include <cuda_runtime.h>
#include <cstddef>

// Problem constants
#define B_   32
#define T_   2048
#define D_   256
#define H_   256
#define CS_  32
#define NN_  8
#define G_   1040      // 4*H + 2*N
#define KK_  512       // D + H (fused GEMM depth)
#define M_   4096      // 2 dirs * T lanes

// ---------------- scratch (static device memory; no allocations) ----------------
__device__ float g_Bmat[2][KK_][G_];     // [dir][k][g]  transposed weights (ih cols reversed for dir 1)
__device__ float g_bias[G_];             // b_ih + b_hh
__device__ float g_h[2 * T_ * H_];       // hidden state per dir/lane
__device__ float g_c[2 * T_ * H_];       // cell state per dir/lane (N*CS = 256 flat)
__device__ float g_gates[(size_t)M_ * G_];
__device__ int   g_off[B_];              // output row offsets (prefix sum of seq_lens)
__device__ int   g_sl[B_];               // seq lens normalized to int32

// ---------------- prep: transpose weights, combine bias, zero state, offsets ----
__global__ void prep_kernel(const float* __restrict__ W_ih, const float* __restrict__ b_ih,
                            const float* __restrict__ W_hh, const float* __restrict__ b_hh,
                            const void* __restrict__ sl_raw) {
    int tid = blockIdx.x * blockDim.x + threadIdx.x;
    int stride = gridDim.x * blockDim.x;
    // build B matrices: [W_ih (maybe feature-reversed) ; W_hh] transposed to [k][g]
    for (int i = tid; i < 2 * KK_ * G_; i += stride) {
        int dir = i / (KK_ * G_);
        int r   = i % (KK_ * G_);
        int k = r / G_, g = r % G_;
        float v;
        if (k < D_) {
            int d = dir ? (D_ - 1 - k) : k;   // backward dir: features reversed
            v = W_ih[g * D_ + d];
        } else {
            v = W_hh[g * H_ + (k - D_)];
        }
        g_Bmat[dir][k][g] = v;
    }
    // zero h and c
    for (int i = tid; i < 2 * T_ * H_; i += stride) { g_h[i] = 0.f; g_c[i] = 0.f; }
    // combined bias
    if (tid < G_) g_bias[tid] = b_ih[tid] + b_hh[tid];
    // seq_lens: detect int32 vs int64 on device. Values are in [1, 2048], sorted.
    // If buffer is little-endian int64, word 1 (high half of elem 0) == 0;
    // if int32, word 1 is the 2nd seq len >= 1.
    if (tid == 0) {
        const int* s32 = (const int*)sl_raw;
        const long long* s64 = (const long long*)sl_raw;
        bool is64 = (s32[1] == 0);
        int acc = 0;
        for (int b = 0; b < B_; b++) {
            int v = is64 ? (int)s64[b] : s32[b];
            g_sl[b]  = v;
            g_off[b] = acc;
            acc += v;
        }
    }
}

// ---------------- per-step GEMM: gates = [x_b | h] @ Bmat + bias ----------------
// M=4096 (dir-major, 2048 lanes each), N=1040 (padded tiles), K=512
#define BM 128
#define BN 128
#define BKC 16

__global__ __launch_bounds__(256, 2) void step_gemm(const float* __restrict__ x, int b) {
    __shared__ float As[BKC][BM + 4];
    __shared__ float Bs[BKC][BN + 4];

    int n0 = blockIdx.x * BN;
    int m0 = blockIdx.y * BM;
    int dir = m0 >> 11;          // BM=128 divides 2048 -> block is single-direction
    int t0  = m0 & (T_ - 1);

    int tid = threadIdx.x;
    int am = tid >> 1, ak = (tid & 1) * 8;    // A loader: row am, 8 k's
    int bk = tid >> 4, bg = (tid & 15) * 8;   // B loader: k-row bk, 8 g's
    int ty = tid >> 4, tx = tid & 15;         // compute mapping: 8x8 per thread

    const float* xrow = x + ((size_t)b * T_ + (t0 + am)) * D_;
    const float* hrow = g_h + ((size_t)dir * T_ + (t0 + am)) * H_;

    float acc[8][8];
#pragma unroll
    for (int i = 0; i < 8; i++)
#pragma unroll
        for (int j = 0; j < 8; j++) acc[i][j] = 0.f;

    bool bvalid = (n0 + bg) < G_;   // 1040 % 8 == 0 -> whole 8-wide group valid or not

    for (int k0 = 0; k0 < KK_; k0 += BKC) {
        // load A tile (x part for k<256, h part for k>=256); tiles never straddle
        const float* ap = (k0 < D_) ? (xrow + k0 + ak) : (hrow + (k0 - D_) + ak);
        float4 a0 = *(const float4*)ap;
        float4 a1 = *(const float4*)(ap + 4);
        As[ak + 0][am] = a0.x; As[ak + 1][am] = a0.y; As[ak + 2][am] = a0.z; As[ak + 3][am] = a0.w;
        As[ak + 4][am] = a1.x; As[ak + 5][am] = a1.y; As[ak + 6][am] = a1.z; As[ak + 7][am] = a1.w;

        float4 b0 = make_float4(0.f, 0.f, 0.f, 0.f);
        float4 b1 = make_float4(0.f, 0.f, 0.f, 0.f);
        if (bvalid) {
            const float* bp = &g_Bmat[dir][k0 + bk][n0 + bg];
            b0 = *(const float4*)bp;
            b1 = *(const float4*)(bp + 4);
        }
        *(float4*)&Bs[bk][bg]     = b0;
        *(float4*)&Bs[bk][bg + 4] = b1;
        __syncthreads();

#pragma unroll
        for (int kk = 0; kk < BKC; kk++) {
            float4 af0 = *(const float4*)&As[kk][ty * 8];
            float4 af1 = *(const float4*)&As[kk][ty * 8 + 4];
            float4 bf0 = *(const float4*)&Bs[kk][tx * 8];
            float4 bf1 = *(const float4*)&Bs[kk][tx * 8 + 4];
            float a[8] = {af0.x, af0.y, af0.z, af0.w, af1.x, af1.y, af1.z, af1.w};
            float bb[8] = {bf0.x, bf0.y, bf0.z, bf0.w, bf1.x, bf1.y, bf1.z, bf1.w};
#pragma unroll
            for (int i = 0; i < 8; i++)
#pragma unroll
                for (int j = 0; j < 8; j++) acc[i][j] = fmaf(a[i], bb[j], acc[i][j]);
        }
        __syncthreads();
    }

    // epilogue: add bias, store gates (vectorized; whole 8-wide group in/out of range)
    int gbase = n0 + tx * 8;
    if (gbase < G_) {
        float4 bias0 = *(const float4*)&g_bias[gbase];
        float4 bias1 = *(const float4*)&g_bias[gbase + 4];
#pragma unroll
        for (int i = 0; i < 8; i++) {
            int m = m0 + ty * 8 + i;
            float* gp = &g_gates[(size_t)m * G_ + gbase];
            float4 o0 = make_float4(acc[i][0] + bias0.x, acc[i][1] + bias0.y,
                                    acc[i][2] + bias0.z, acc[i][3] + bias0.w);
            float4 o1 = make_float4(acc[i][4] + bias1.x, acc[i][5] + bias1.y,
                                    acc[i][6] + bias1.z, acc[i][7] + bias1.w);
            *(float4*)gp       = o0;
            *(float4*)(gp + 4) = o1;
        }
    }
}

// ---------------- per-step gate update ----------------
__device__ __forceinline__ float sigmoidf_(float xx) { return 1.f / (1.f + __expf(-xx)); }
__device__ __forceinline__ float tanhf_(float xx)    { return 1.f - 2.f / (1.f + __expf(2.f * xx)); }

__global__ __launch_bounds__(256) void step_gate(float* __restrict__ out, int b) {
    int m   = blockIdx.x;              // 0..4095 lane (dir-major)
    int dir = m >> 11;
    int t   = m & (T_ - 1);
    const float* grow = g_gates + (size_t)m * G_;

    __shared__ float s_cin[NN_], s_cfg[NN_];
    int tid = threadIdx.x;             // 256 threads: n = tid>>5, s = tid&31

    if (tid < 2) {
        // cumsoftmax over 8 master-gate values
        const float* gm = grow + tid * NN_;
        float v[NN_], mx = -1e30f;
#pragma unroll
        for (int i = 0; i < NN_; i++) { v[i] = gm[i]; mx = fmaxf(mx, v[i]); }
        float s = 0.f;
#pragma unroll
        for (int i = 0; i < NN_; i++) { v[i] = __expf(v[i] - mx); s += v[i]; }
        float inv = 1.f / s, c = 0.f;
        float* dst = tid ? s_cfg : s_cin;
#pragma unroll
        for (int i = 0; i < NN_; i++) {
            c += v[i] * inv;
            dst[i] = tid ? c : (1.f - c);   // cin = 1 - cumsoftmax, cfg = cumsoftmax
        }
    }
    __syncthreads();

    int n = tid >> 5;
    // rest = gates[16:].reshape(4N, CS); og rows 0..7, cg 8..15, ig 16..23, fg 24..31
    float og = grow[16 + tid];
    float cg = grow[16 + 8 * CS_ + tid];
    float ig = grow[16 + 16 * CS_ + tid];
    float fg = grow[16 + 24 * CS_ + tid];

    float ci = s_cin[n], cf = s_cfg[n];
    float ov = cf * ci;
    float fv = sigmoidf_(fg) * ov + (cf - ov);
    float iv = sigmoidf_(ig) * ov + (ci - ov);

    size_t hidx = ((size_t)dir * T_ + t) * H_ + tid;
    float cy = fv * g_c[hidx] + iv * tanhf_(cg);
    g_c[hidx] = cy;
    float hy = sigmoidf_(og) * tanhf_(cy);
    g_h[hidx] = hy;

    if (t < g_sl[b]) {
        out[((size_t)(g_off[b] + t)) * (2 * H_) + dir * H_ + tid] = hy;
    }
}

// ---------------- launch ----------------
extern "C" void kernel_launch(void* const* d_in, const int* in_sizes, int n_in,
                              void* d_out, int out_size) {
    const float* x     = (const float*)d_in[0];
    const void*  sl    = d_in[1];
    const float* W_ih  = (const float*)d_in[2];
    const float* b_ih  = (const float*)d_in[3];
    const float* W_hh  = (const float*)d_in[4];
    const float* b_hh  = (const float*)d_in[5];
    float*       out   = (float*)d_out;

    prep_kernel<<<1024, 256>>>(W_ih, b_ih, W_hh, b_hh, sl);

    dim3 gg((G_ + BN - 1) / BN, M_ / BM);   // 9 x 32
    for (int b = 0; b < B_; b++) {
        step_gemm<<<gg, 256>>>(x, b);
        step_gate<<<M_, 256>>>(out, b);
    }
}

// round 4
// speedup vs baseline: 1.9288x; 1.9288x over previous
#include <cuda_runtime.h>
#include <cuda_bf16.h>
#include <cstdint>
#include <cstddef>

// Problem constants
#define B_   32
#define T_   2048
#define D_   256
#define H_   256
#define CS_  32
#define NN_  8
#define G_   1040      // 4*H + 2*N
#define GP_  1152      // padded to 9 tiles of 128
#define KK_  512       // D + H
#define M_   4096      // 2 dirs * 2048 lanes
#define MPROJ_ 131072  // 2 dirs * B * T rows

// ---------------- static device scratch ----------------
__device__ __nv_bfloat16 g_Whi[2][GP_][KK_];   // [dir][g][k]; dir1 input cols feature-reversed
__device__ __nv_bfloat16 g_Wlo[2][GP_][KK_];
__device__ __nv_bfloat16 g_xhi[(size_t)B_ * T_ * D_];
__device__ __nv_bfloat16 g_xlo[(size_t)B_ * T_ * D_];
__device__ __nv_bfloat16 g_hhi[2 * T_ * H_];
__device__ __nv_bfloat16 g_hlo[2 * T_ * H_];
__device__ float g_c[2 * T_ * H_];
__device__ float g_bias[GP_];
__device__ float g_tin[(size_t)MPROJ_ * GP_];   // precomputed input projection
__device__ float g_gates[(size_t)M_ * GP_];
__device__ int   g_off[B_];
__device__ int   g_sl[B_];

// ---------------- helpers ----------------
__device__ __forceinline__ uint32_t smem_u32(const void* p) {
    uint32_t a;
    asm("{ .reg .u64 t; cvta.to.shared.u64 t, %1; cvt.u32.u64 %0, t; }" : "=r"(a) : "l"(p));
    return a;
}
__device__ __forceinline__ void ldsm_x4(uint32_t* r, uint32_t addr) {
    asm volatile("ldmatrix.sync.aligned.m8n8.x4.shared.b16 {%0,%1,%2,%3}, [%4];"
        : "=r"(r[0]), "=r"(r[1]), "=r"(r[2]), "=r"(r[3]) : "r"(addr));
}
__device__ __forceinline__ void mma16816(float* c, const uint32_t* a, const uint32_t* b) {
    asm volatile("mma.sync.aligned.m16n8k16.row.col.f32.bf16.bf16.f32 "
        "{%0,%1,%2,%3}, {%4,%5,%6,%7}, {%8,%9}, {%0,%1,%2,%3};"
        : "+f"(c[0]), "+f"(c[1]), "+f"(c[2]), "+f"(c[3])
        : "r"(a[0]), "r"(a[1]), "r"(a[2]), "r"(a[3]), "r"(b[0]), "r"(b[1]));
}

// ---------------- prep ----------------
__global__ void prep_kernel(const float* __restrict__ x,
                            const float* __restrict__ W_ih, const float* __restrict__ b_ih,
                            const float* __restrict__ W_hh, const float* __restrict__ b_hh,
                            const void* __restrict__ sl_raw) {
    int tid = blockIdx.x * blockDim.x + threadIdx.x;
    int stride = gridDim.x * blockDim.x;
    for (int i = tid; i < 2 * GP_ * KK_; i += stride) {
        int dir = i / (GP_ * KK_);
        int r   = i % (GP_ * KK_);
        int g = r / KK_, k = r % KK_;
        float v = 0.f;
        if (g < G_) {
            if (k < D_) v = W_ih[g * D_ + (dir ? (D_ - 1 - k) : k)];
            else        v = W_hh[g * H_ + (k - D_)];
        }
        __nv_bfloat16 hi = __float2bfloat16(v);
        g_Whi[dir][g][k] = hi;
        g_Wlo[dir][g][k] = __float2bfloat16(v - __bfloat162float(hi));
    }
    for (size_t i = tid; i < (size_t)B_ * T_ * D_; i += stride) {
        float v = x[i];
        __nv_bfloat16 hi = __float2bfloat16(v);
        g_xhi[i] = hi;
        g_xlo[i] = __float2bfloat16(v - __bfloat162float(hi));
    }
    for (int i = tid; i < 2 * T_ * H_; i += stride) {
        g_hhi[i] = __float2bfloat16(0.f);
        g_hlo[i] = __float2bfloat16(0.f);
        g_c[i] = 0.f;
    }
    if (tid < GP_) g_bias[tid] = (tid < G_) ? (b_ih[tid] + b_hh[tid]) : 0.f;
    if (tid == 0) {
        const int* s32 = (const int*)sl_raw;
        const long long* s64 = (const long long*)sl_raw;
        bool is64 = (s32[1] == 0);
        int acc = 0;
        for (int b = 0; b < B_; b++) {
            int v = is64 ? (int)s64[b] : s32[b];
            g_sl[b] = v; g_off[b] = acc; acc += v;
        }
    }
}

// ---------------- bf16 mma.sync GEMM (3-term split) ----------------
// C[m][g] = sum_k A[m][k] * W[g][k] over K=256.
// IS_STEP: A = h (bf16 hi/lo), W cols 256..511, epilogue adds t_in + bias -> g_gates
// !IS_STEP: A = x, W cols 0..255, epilogue stores raw -> g_tin
template <bool IS_STEP>
__global__ __launch_bounds__(256) void gemm_mma(int bidx) {
    __shared__ __align__(16) __nv_bfloat16 As[2][128][40];   // hi, lo
    __shared__ __align__(16) __nv_bfloat16 Bs[2][128][40];

    int tid = threadIdx.x, lane = tid & 31, wid = tid >> 5;
    int wm = wid & 3, wn = wid >> 2;
    int n0 = blockIdx.x * 128;
    int m0 = blockIdx.y * 128;

    int dir, kofsW;
    const __nv_bfloat16 *Ahi_g, *Alo_g;
    if (IS_STEP) {
        dir = m0 >> 11;
        int t0 = m0 & (T_ - 1);
        Ahi_g = g_hhi + ((size_t)dir * T_ + t0) * H_;
        Alo_g = g_hlo + ((size_t)dir * T_ + t0) * H_;
        kofsW = D_;
    } else {
        dir = m0 >> 16;
        int r = m0 & 65535;     // b*2048 + t (x identical both dirs; reversal in W)
        Ahi_g = g_xhi + (size_t)r * D_;
        Alo_g = g_xlo + (size_t)r * D_;
        kofsW = 0;
    }

    float acc[2][8][4];
#pragma unroll
    for (int im = 0; im < 2; im++)
#pragma unroll
        for (int in_ = 0; in_ < 8; in_++)
#pragma unroll
            for (int j = 0; j < 4; j++) acc[im][in_][j] = 0.f;

    for (int k0 = 0; k0 < 256; k0 += 32) {
        // load 4 tiles: As[0](Ahi), As[1](Alo), Bs[0](Whi), Bs[1](Wlo)
#pragma unroll
        for (int i = 0; i < 8; i++) {
            int s = tid + i * 256;            // 0..2047
            int tile = s >> 9;
            int idx  = s & 511;
            int r  = idx >> 2;
            int ks = (idx & 3) * 8;           // 16B segment
            const __nv_bfloat16* src;
            if      (tile == 0) src = Ahi_g + (size_t)r * 256 + k0 + ks;
            else if (tile == 1) src = Alo_g + (size_t)r * 256 + k0 + ks;
            else if (tile == 2) src = &g_Whi[dir][n0 + r][kofsW + k0 + ks];
            else                src = &g_Wlo[dir][n0 + r][kofsW + k0 + ks];
            uint4 v = *(const uint4*)src;
            __nv_bfloat16* dst = (tile == 0) ? &As[0][r][ks] :
                                 (tile == 1) ? &As[1][r][ks] :
                                 (tile == 2) ? &Bs[0][r][ks] : &Bs[1][r][ks];
            *(uint4*)dst = v;
        }
        __syncthreads();

#pragma unroll
        for (int kk = 0; kk < 32; kk += 16) {
            uint32_t ah[2][4], al[2][4], bh[4][4], bl[4][4];
#pragma unroll
            for (int im = 0; im < 2; im++) {
                int arow = wm * 32 + im * 16 + (lane & 15);
                int acol = kk + ((lane >> 4) << 3);
                ldsm_x4(ah[im], smem_u32(&As[0][arow][acol]));
                ldsm_x4(al[im], smem_u32(&As[1][arow][acol]));
            }
#pragma unroll
            for (int p = 0; p < 4; p++) {
                int brow = wn * 64 + p * 16 + (lane & 7) + ((lane >> 4) & 1) * 8;
                int bcol = kk + (((lane >> 3) & 1) << 3);
                ldsm_x4(bh[p], smem_u32(&Bs[0][brow][bcol]));
                ldsm_x4(bl[p], smem_u32(&Bs[1][brow][bcol]));
            }
#pragma unroll
            for (int im = 0; im < 2; im++)
#pragma unroll
                for (int in_ = 0; in_ < 8; in_++) {
                    const uint32_t* B0 = &bh[in_ >> 1][(in_ & 1) * 2];
                    const uint32_t* B1 = &bl[in_ >> 1][(in_ & 1) * 2];
                    mma16816(acc[im][in_], ah[im], B0);   // hi*hi
                    mma16816(acc[im][in_], ah[im], B1);   // hi*lo
                    mma16816(acc[im][in_], al[im], B0);   // lo*hi
                }
        }
        __syncthreads();
    }

    // epilogue
#pragma unroll
    for (int im = 0; im < 2; im++)
#pragma unroll
        for (int in_ = 0; in_ < 8; in_++) {
            int row = m0 + wm * 32 + im * 16 + (lane >> 2);
            int col = n0 + wn * 64 + in_ * 8 + ((lane & 3) << 1);
            float* c = acc[im][in_];
            if (IS_STEP) {
                int t = row & (T_ - 1);
                int d = row >> 11;
                size_t trow = (size_t)(d * 65536 + bidx * 2048 + t);
                float2 t0 = *(const float2*)&g_tin[trow * GP_ + col];
                float2 t1 = *(const float2*)&g_tin[(trow + 8) * GP_ + col];
                float2 bb = *(const float2*)&g_bias[col];
                float2 o0 = make_float2(c[0] + t0.x + bb.x, c[1] + t0.y + bb.y);
                float2 o1 = make_float2(c[2] + t1.x + bb.x, c[3] + t1.y + bb.y);
                *(float2*)&g_gates[(size_t)row * GP_ + col] = o0;
                *(float2*)&g_gates[(size_t)(row + 8) * GP_ + col] = o1;
            } else {
                *(float2*)&g_tin[(size_t)row * GP_ + col] = make_float2(c[0], c[1]);
                *(float2*)&g_tin[(size_t)(row + 8) * GP_ + col] = make_float2(c[2], c[3]);
            }
        }
}

// ---------------- per-step gate update ----------------
__device__ __forceinline__ float sigmoidf_(float xx) { return 1.f / (1.f + __expf(-xx)); }
__device__ __forceinline__ float tanhf_(float xx)    { return 1.f - 2.f / (1.f + __expf(2.f * xx)); }

__global__ __launch_bounds__(256) void step_gate(float* __restrict__ out, int b) {
    int m   = blockIdx.x;
    int dir = m >> 11;
    int t   = m & (T_ - 1);
    const float* grow = g_gates + (size_t)m * GP_;

    __shared__ float s_cin[NN_], s_cfg[NN_];
    int tid = threadIdx.x;

    if (tid < 2) {
        const float* gm = grow + tid * NN_;
        float v[NN_], mx = -1e30f;
#pragma unroll
        for (int i = 0; i < NN_; i++) { v[i] = gm[i]; mx = fmaxf(mx, v[i]); }
        float s = 0.f;
#pragma unroll
        for (int i = 0; i < NN_; i++) { v[i] = __expf(v[i] - mx); s += v[i]; }
        float inv = 1.f / s, cacc = 0.f;
        float* dst = tid ? s_cfg : s_cin;
#pragma unroll
        for (int i = 0; i < NN_; i++) {
            cacc += v[i] * inv;
            dst[i] = tid ? cacc : (1.f - cacc);
        }
    }
    __syncthreads();

    int n = tid >> 5;
    float og = grow[16 + tid];
    float cg = grow[16 + 8 * CS_ + tid];
    float ig = grow[16 + 16 * CS_ + tid];
    float fg = grow[16 + 24 * CS_ + tid];

    float ci = s_cin[n], cf = s_cfg[n];
    float ov = cf * ci;
    float fv = sigmoidf_(fg) * ov + (cf - ov);
    float iv = sigmoidf_(ig) * ov + (ci - ov);

    size_t hidx = ((size_t)dir * T_ + t) * H_ + tid;
    float cy = fv * g_c[hidx] + iv * tanhf_(cg);
    g_c[hidx] = cy;
    float hy = sigmoidf_(og) * tanhf_(cy);
    __nv_bfloat16 hi = __float2bfloat16(hy);
    g_hhi[hidx] = hi;
    g_hlo[hidx] = __float2bfloat16(hy - __bfloat162float(hi));

    if (t < g_sl[b]) {
        out[((size_t)(g_off[b] + t)) * (2 * H_) + dir * H_ + tid] = hy;
    }
}

// ---------------- launch ----------------
extern "C" void kernel_launch(void* const* d_in, const int* in_sizes, int n_in,
                              void* d_out, int out_size) {
    const float* x    = (const float*)d_in[0];
    const void*  sl   = d_in[1];
    const float* W_ih = (const float*)d_in[2];
    const float* b_ih = (const float*)d_in[3];
    const float* W_hh = (const float*)d_in[4];
    const float* b_hh = (const float*)d_in[5];
    float*       out  = (float*)d_out;

    prep_kernel<<<4096, 256>>>(x, W_ih, b_ih, W_hh, b_hh, sl);

    // input projection for all (dir, b, t) rows at once
    gemm_mma<false><<<dim3(GP_ / 128, MPROJ_ / 128), 256>>>(0);

    for (int b = 0; b < B_; b++) {
        gemm_mma<true><<<dim3(GP_ / 128, M_ / 128), 256>>>(b);
        step_gate<<<M_, 256>>>(out, b);
    }
}